// round 15
// baseline (speedup 1.0000x reference)
#include <cuda_runtime.h>
#include <cuda_bf16.h>
#include <float.h>

#define Bn 128
#define On 1024
#define In 1024
#define EPSc 1e-7f
#define L2E 1.4426950408889634f
#define CUT_NATS 20.794415417f   // 30*ln2: drop softmax terms with weight < 2^-30
#define CAP 96                   // per-warp candidate capacity (dense fallback beyond)
#define NBLK 256

// Scratch (no allocs allowed) — every element rewritten each run (replay-safe);
// barrier epoch is monotonic by design (sense-reversing).
__device__ float    g_c2_im[In * On];    // C^2, i-major [i][o]
__device__ float    g_tmin[In * 32];     // per (i, 32-o tile) min of C^2
__device__ float    g_data_im[In * Bn];  // data transposed [i][b]
__device__ unsigned g_epoch = 0;         // grid-barrier generation (monotonic)
__device__ unsigned g_count = 0;         // grid-barrier arrivals

__device__ __forceinline__ float rsq(float x) {
    float r;
    asm("rsqrt.approx.ftz.f32 %0, %1;" : "=f"(r) : "f"(x));
    return r;
}
__device__ __forceinline__ float ex2(float x) {
    float r;
    asm("ex2.approx.ftz.f32 %0, %1;" : "=f"(r) : "f"(x));
    return r;
}

// ---------------- single fused kernel: prep -> grid barrier -> sparse softmax ----
// __launch_bounds__(256,2): compiler-guaranteed >=2 CTAs/SM -> all 256 CTAs
// resident in one wave (296 slots) -> software grid barrier cannot deadlock.
__global__ void __launch_bounds__(256, 2) kall(
        float* __restrict__ out, const float* __restrict__ data,
        const float* __restrict__ ix, const float* __restrict__ iy,
        const float* __restrict__ ox, const float* __restrict__ oy,
        const float* __restrict__ la, const float* __restrict__ lm) {
    __shared__ float tile[32][33];
    __shared__ int   s_o[8][CAP];
    __shared__ float s_c2[8][CAP];

    int t = threadIdx.x;
    int tx = t & 31, ty = t >> 5;

    // ================= PHASE 1: C^2 + tile-min + transposes + zeroing ============
    // 4 C^2 tiles per block (1024 total). IEEE div.rn kept — C is
    // cancellation-amplified; fast-div error shifts the softmax exponent.
#pragma unroll 1
    for (int q = 0; q < 4; q++) {
        int tidx = blockIdx.x * 4 + q;
        int otile = tidx & 31;
        int ob  = otile * 32;
        int ibt = (tidx >> 5) * 32;
#pragma unroll
        for (int k = 0; k < 4; k++) {
            int o = ob + ty + k * 8;
            int idx = o * In + ibt + tx;     // coalesced over tx
            float c = (ix[idx] / iy[idx] + la[idx]) * (1.0f + lm[idx]) - ox[idx] / oy[idx];
            tile[ty + k * 8][tx] = c * c;
        }
        __syncthreads();
#pragma unroll
        for (int k = 0; k < 4; k++) {
            int il = ty + k * 8;             // i within tile
            float v = tile[tx][il];          // tx = o within tile
            g_c2_im[(ibt + il) * In + ob + tx] = v;
            float mn = v;
#pragma unroll
            for (int s = 16; s; s >>= 1) mn = fminf(mn, __shfl_xor_sync(0xffffffffu, mn, s));
            if (tx == 0) g_tmin[(ibt + il) * 32 + otile] = mn;
        }
        __syncthreads();
    }

    // data transpose [128,1024] -> [1024,128] (blocks 0..127)
    if (blockIdx.x < 128) {
        int bb = (blockIdx.x & 3) * 32;
        int ib = (blockIdx.x >> 2) * 32;
#pragma unroll
        for (int k = 0; k < 4; k++)
            tile[ty + k * 8][tx] = data[(bb + ty + k * 8) * In + ib + tx];
        __syncthreads();
#pragma unroll
        for (int k = 0; k < 4; k++) {
            int il = ty + k * 8;
            g_data_im[(ib + il) * Bn + bb + tx] = tile[tx][il];
        }
    }

    // zero the output: out = 32768 float4 total / 256 blocks = 128 float4 each.
    // (R14 bug: wrote 512/block across 256 blocks = 4x buffer -> OOB stomp.)
    if (t < 128)
        ((float4*)out)[blockIdx.x * 128 + t] = make_float4(0.f, 0.f, 0.f, 0.f);

    // ================= GRID BARRIER (sense-reversing, replay-safe) ===============
    __threadfence();                          // release phase-1 writes
    if (t == 0) {
        unsigned e = *((volatile unsigned*)&g_epoch);
        unsigned c = atomicAdd(&g_count, 1);
        if (c == NBLK - 1) {
            atomicExch(&g_count, 0);          // reset for next replay
            __threadfence();
            atomicAdd(&g_epoch, 1);           // release all waiters
        } else {
            while (*((volatile unsigned*)&g_epoch) == e) { }
        }
    }
    __syncthreads();
    __threadfence();                          // acquire side

    // ================= PHASE 2: hierarchical sparse softmax ======================
    // 2048 warps; warp gw = (i, half): 128B tile-min load -> c2min -> T over its
    // 64 b's -> load only tiles with tmin <= T -> exact check -> eval ~3 cands.
    int lane = tx, warp = ty;
    int gw = blockIdx.x * 8 + warp;
    int i = gw >> 1;
    int half = gw & 1;
    unsigned lmask = (1u << lane) - 1u;

    float tmin = g_tmin[i * 32 + lane];       // one coalesced 128B load
    float mn = tmin;
#pragma unroll
    for (int s = 16; s; s >>= 1) mn = fminf(mn, __shfl_xor_sync(0xffffffffu, mn, s));
    float c2min = mn;

    const float* dcol = g_data_im + (size_t)i * Bn + 64 * half;
    float dd[2], g2[2], Bm[2];
    float kmax = 0.f;
#pragma unroll
    for (int r = 0; r < 2; r++) {
        dd[r] = dcol[lane + 32 * r];          // coalesced
        float g = 1.0f / (1.0f + __expf(-dd[r]));
        g2[r] = g * g;
        float smax = rsq(fmaf(c2min, g2[r], EPSc));
        Bm[r] = -smax * L2E;
        float q = smax - CUT_NATS;
        float keep = (q > 0.f) ? (1.0f / (q * q) - EPSc) / g2[r] : FLT_MAX;
        kmax = fmaxf(kmax, keep);
    }
#pragma unroll
    for (int s = 16; s; s >>= 1) kmax = fmaxf(kmax, __shfl_xor_sync(0xffffffffu, kmax, s));
    float T = kmax;                           // conservative for this warp's 64 b's

    unsigned selmask = __ballot_sync(0xffffffffu, tmin <= T);
    const float* row = g_c2_im + (size_t)i * In;
    int base = 0;
    unsigned m = selmask;
    while (m) {
        int ot = __ffs(m) - 1;                // warp-uniform
        m &= m - 1;
        float v = row[ot * 32 + lane];        // 128B coalesced (L2-warm)
        bool pred = (v <= T);
        unsigned bal = __ballot_sync(0xffffffffu, pred);
        if (pred) {
            int pos = base + __popc(bal & lmask);
            if (pos < CAP) {
                s_o[warp][pos]  = ot * 32 + lane;
                s_c2[warp][pos] = v;
            }
        }
        base += __popc(bal);
    }
    int cnt = base;
    __syncwarp();

    if (cnt <= CAP) {
        // sparse path: lanes walk the shared tiny list (LDS broadcast)
        float S[2] = {0.f, 0.f};
        for (int k = 0; k < cnt; k++) {
            float c2 = s_c2[warp][k];
#pragma unroll
            for (int r = 0; r < 2; r++)
                S[r] += ex2(fmaf(rsq(fmaf(c2, g2[r], EPSc)), L2E, Bm[r]));
        }
        float coef[2];
#pragma unroll
        for (int r = 0; r < 2; r++) coef[r] = __fdividef(dd[r], S[r]);
        for (int k = 0; k < cnt; k++) {
            int o = s_o[warp][k];
            float c2 = s_c2[warp][k];
#pragma unroll
            for (int r = 0; r < 2; r++) {
                float e = ex2(fmaf(rsq(fmaf(c2, g2[r], EPSc)), L2E, Bm[r]));
                atomicAdd(&out[(size_t)(64 * half + lane + 32 * r) * On + o], coef[r] * e);
            }
        }
    } else {
        // dense fallback — correct for any data; statistically never taken
        float S[2] = {0.f, 0.f};
        for (int k = 0; k < In; k++) {
            float c2 = row[k];
#pragma unroll
            for (int r = 0; r < 2; r++)
                S[r] += ex2(fmaf(rsq(fmaf(c2, g2[r], EPSc)), L2E, Bm[r]));
        }
        float coef[2];
#pragma unroll
        for (int r = 0; r < 2; r++) coef[r] = __fdividef(dd[r], S[r]);
        for (int k = 0; k < In; k++) {
            float c2 = row[k];
#pragma unroll
            for (int r = 0; r < 2; r++) {
                float e = ex2(fmaf(rsq(fmaf(c2, g2[r], EPSc)), L2E, Bm[r]));
                atomicAdd(&out[(size_t)(64 * half + lane + 32 * r) * On + k], coef[r] * e);
            }
        }
    }
}

extern "C" void kernel_launch(void* const* d_in, const int* in_sizes, int n_in,
                              void* d_out, int out_size) {
    const float* data = (const float*)d_in[0];
    const float* ix   = (const float*)d_in[1];
    const float* iy   = (const float*)d_in[2];
    const float* ox   = (const float*)d_in[3];
    const float* oy   = (const float*)d_in[4];
    const float* la   = (const float*)d_in[5];
    const float* lm   = (const float*)d_in[6];
    float* out = (float*)d_out;

    kall<<<NBLK, 256>>>(out, data, ix, iy, ox, oy, la, lm);
}

// round 16
// speedup vs baseline: 1.0884x; 1.0884x over previous
#include <cuda_runtime.h>
#include <cuda_bf16.h>
#include <float.h>

#define Bn 128
#define On 1024
#define In 1024
#define EPSc 1e-7f
#define L2E 1.4426950408889634f
#define CUT_NATS 20.794415417f   // 30*ln2: drop softmax terms with weight < 2^-30
#define CAP 96                   // per-warp candidate capacity (dense fallback beyond)
#define NBLK 1024

// Scratch (no allocs allowed) — every element rewritten each run (replay-safe).
__device__ float    g_c2_im[In * On];    // C^2, i-major [i][o]
__device__ float    g_tmin[In * 32];     // per (i, 32-o tile) min of C^2
__device__ unsigned g_count = 0;         // barrier arrivals (winner resets -> release)

__device__ __forceinline__ float rsq(float x) {
    float r;
    asm("rsqrt.approx.ftz.f32 %0, %1;" : "=f"(r) : "f"(x));
    return r;
}
__device__ __forceinline__ float ex2(float x) {
    float r;
    asm("ex2.approx.ftz.f32 %0, %1;" : "=f"(r) : "f"(x));
    return r;
}

// ---------------- single fused kernel: prep -> count barrier -> sparse softmax ----
// 1024 blocks x 128 threads, __launch_bounds__(128,8): regs<=64 -> occupancy
// limit 8 CTAs/SM -> 1184 slots >= 1024 -> ALL blocks resident in wave 1, so
// the software barrier cannot deadlock. One C^2 tile per block (good latency
// overlap at ~7 blocks/SM, unlike R15's 4-tile serial blocks at occ 2).
__global__ void __launch_bounds__(128, 8) kall(
        float* __restrict__ out, const float* __restrict__ data,
        const float* __restrict__ ix, const float* __restrict__ iy,
        const float* __restrict__ ox, const float* __restrict__ oy,
        const float* __restrict__ la, const float* __restrict__ lm) {
    __shared__ float tile[32][33];
    __shared__ int   s_o[4][CAP];
    __shared__ float s_c2[4][CAP];

    int t = threadIdx.x;
    int tx = t & 31, ty = t >> 5;          // 4 warps

    // ================= PHASE 1: one C^2 tile + tile-min + out zeroing ============
    // IEEE div.rn kept — C is cancellation-amplified; fast-div error shifts the
    // softmax exponent by O(0.1) nats.
    {
        int otile = blockIdx.x & 31;
        int ob  = otile * 32;
        int ibt = (blockIdx.x >> 5) * 32;
#pragma unroll
        for (int k = 0; k < 8; k++) {
            int o = ob + ty + k * 4;
            int idx = o * In + ibt + tx;     // coalesced over tx (consecutive i)
            float c = (ix[idx] / iy[idx] + la[idx]) * (1.0f + lm[idx]) - ox[idx] / oy[idx];
            tile[ty + k * 4][tx] = c * c;
        }
        __syncthreads();
#pragma unroll
        for (int k = 0; k < 8; k++) {
            int il = ty + k * 4;             // i within tile (fixed per warp per k)
            float v = tile[tx][il];          // tx = o within tile; stride-33 conflict-free
            g_c2_im[(ibt + il) * In + ob + tx] = v;
            float mn = v;
#pragma unroll
            for (int s = 16; s; s >>= 1) mn = fminf(mn, __shfl_xor_sync(0xffffffffu, mn, s));
            if (tx == 0) g_tmin[(ibt + il) * 32 + otile] = mn;
        }
    }

    // zero the output: 32768 float4 / 1024 blocks = 32 per block
    if (t < 32)
        ((float4*)out)[blockIdx.x * 32 + t] = make_float4(0.f, 0.f, 0.f, 0.f);

    // ================= COUNT BARRIER (same-address ordering; replay-safe) ========
    // Arrive: fence + atomicAdd. Waiters spin on count != 0 (reads of the SAME
    // address after own RMW are ordered -> no stale-pre-read race). The last
    // arrival resets count to 0, releasing everyone and re-arming for replay.
    __threadfence();                          // release phase-1 writes
    if (t == 0) {
        unsigned c = atomicAdd(&g_count, 1);
        if (c == NBLK - 1) {
            atomicExch(&g_count, 0);          // release + re-arm
        } else {
            while (*((volatile unsigned*)&g_count) != 0u) { }
        }
    }
    __syncthreads();
    __threadfence();                          // acquire side

    // ================= PHASE 2: hierarchical sparse softmax ======================
    // 2048 tasks (i, half) over the first 2048 of 4096 warps. Per task: 128B
    // tile-min load -> c2min -> T over 64 b's -> load only tiles with
    // tmin <= T -> exact check -> evaluate ~3 candidates -> scatter-add.
    int lane = tx, warp = ty;
    int gw = blockIdx.x * 4 + warp;
    if (gw >= 2 * In) return;
    int i = gw >> 1;
    int half = gw & 1;
    unsigned lmask = (1u << lane) - 1u;

    float tmin = g_tmin[i * 32 + lane];       // one coalesced 128B load (L2-warm)
    float mn = tmin;
#pragma unroll
    for (int s = 16; s; s >>= 1) mn = fminf(mn, __shfl_xor_sync(0xffffffffu, mn, s));
    float c2min = mn;

    // per-b scalars, b = 64*half + lane + 32r; data read directly (L2-resident)
    float dd[2], g2[2], Bm[2];
    float kmax = 0.f;
#pragma unroll
    for (int r = 0; r < 2; r++) {
        dd[r] = data[(size_t)(64 * half + lane + 32 * r) * In + i];
        float g = 1.0f / (1.0f + __expf(-dd[r]));
        g2[r] = g * g;
        float smax = rsq(fmaf(c2min, g2[r], EPSc));
        Bm[r] = -smax * L2E;
        float q = smax - CUT_NATS;
        float keep = (q > 0.f) ? (1.0f / (q * q) - EPSc) / g2[r] : FLT_MAX;
        kmax = fmaxf(kmax, keep);
    }
#pragma unroll
    for (int s = 16; s; s >>= 1) kmax = fmaxf(kmax, __shfl_xor_sync(0xffffffffu, kmax, s));
    float T = kmax;                           // conservative for this warp's 64 b's

    unsigned selmask = __ballot_sync(0xffffffffu, tmin <= T);
    const float* row = g_c2_im + (size_t)i * In;
    int base = 0;
    unsigned m = selmask;
    while (m) {
        int ot = __ffs(m) - 1;                // warp-uniform
        m &= m - 1;
        float v = row[ot * 32 + lane];        // 128B coalesced (L2-warm)
        bool pred = (v <= T);
        unsigned bal = __ballot_sync(0xffffffffu, pred);
        if (pred) {
            int pos = base + __popc(bal & lmask);
            if (pos < CAP) {
                s_o[warp][pos]  = ot * 32 + lane;
                s_c2[warp][pos] = v;
            }
        }
        base += __popc(bal);
    }
    int cnt = base;
    __syncwarp();

    if (cnt <= CAP) {
        // sparse path: lanes walk the shared tiny list (LDS broadcast)
        float S[2] = {0.f, 0.f};
        for (int k = 0; k < cnt; k++) {
            float c2 = s_c2[warp][k];
#pragma unroll
            for (int r = 0; r < 2; r++)
                S[r] += ex2(fmaf(rsq(fmaf(c2, g2[r], EPSc)), L2E, Bm[r]));
        }
        float coef[2];
#pragma unroll
        for (int r = 0; r < 2; r++) coef[r] = __fdividef(dd[r], S[r]);
        for (int k = 0; k < cnt; k++) {
            int o = s_o[warp][k];
            float c2 = s_c2[warp][k];
#pragma unroll
            for (int r = 0; r < 2; r++) {
                float e = ex2(fmaf(rsq(fmaf(c2, g2[r], EPSc)), L2E, Bm[r]));
                atomicAdd(&out[(size_t)(64 * half + lane + 32 * r) * On + o], coef[r] * e);
            }
        }
    } else {
        // dense fallback — correct for any data; statistically never taken
        float S[2] = {0.f, 0.f};
        for (int k = 0; k < In; k++) {
            float c2 = row[k];
#pragma unroll
            for (int r = 0; r < 2; r++)
                S[r] += ex2(fmaf(rsq(fmaf(c2, g2[r], EPSc)), L2E, Bm[r]));
        }
        float coef[2];
#pragma unroll
        for (int r = 0; r < 2; r++) coef[r] = __fdividef(dd[r], S[r]);
        for (int k = 0; k < In; k++) {
            float c2 = row[k];
#pragma unroll
            for (int r = 0; r < 2; r++) {
                float e = ex2(fmaf(rsq(fmaf(c2, g2[r], EPSc)), L2E, Bm[r]));
                atomicAdd(&out[(size_t)(64 * half + lane + 32 * r) * On + k], coef[r] * e);
            }
        }
    }
}

extern "C" void kernel_launch(void* const* d_in, const int* in_sizes, int n_in,
                              void* d_out, int out_size) {
    const float* data = (const float*)d_in[0];
    const float* ix   = (const float*)d_in[1];
    const float* iy   = (const float*)d_in[2];
    const float* ox   = (const float*)d_in[3];
    const float* oy   = (const float*)d_in[4];
    const float* la   = (const float*)d_in[5];
    const float* lm   = (const float*)d_in[6];
    float* out = (float*)d_out;

    kall<<<NBLK, 128>>>(out, data, ix, iy, ox, oy, la, lm);
}

// round 17
// speedup vs baseline: 1.1214x; 1.0304x over previous
#include <cuda_runtime.h>
#include <cuda_bf16.h>
#include <float.h>

#define Bn 128
#define On 1024
#define In 1024
#define EPSc 1e-7f
#define L2E 1.4426950408889634f
#define CUT_NATS 20.794415417f   // 30*ln2: drop softmax terms with weight < 2^-30
#define CAP 96                   // per-warp candidate capacity (dense fallback beyond)
#define NPROD 1024
#define NCONS 128

// Scratch (no allocs allowed). Counters self-reset every run (replay-safe).
__device__ float    g_c2[On * In];     // C^2, o-major (same layout as params)
__device__ float    g_tmin[In * 32];   // per (i, 32-o tile) min of C^2
__device__ unsigned g_zc = 0;          // producers that finished zeroing out
__device__ unsigned g_cnt[32];         // per i-block tile completions (0-init)
__device__ unsigned g_ccnt = 0;        // consumer completions (last one resets all)

__device__ __forceinline__ float rsq(float x) {
    float r;
    asm("rsqrt.approx.ftz.f32 %0, %1;" : "=f"(r) : "f"(x));
    return r;
}
__device__ __forceinline__ float ex2(float x) {
    float r;
    asm("ex2.approx.ftz.f32 %0, %1;" : "=f"(r) : "f"(x));
    return r;
}

// ---- single launch: 1024 producer blocks + 128 consumer blocks (grid tail) ----
// Producers: one 32x32 C^2 tile each (R12-kprep shape; no transpose staging),
// write c2 o-major coalesced + per-i tile-min, then arrive on g_cnt[ib].
// Consumers: gate on their i-block's 32 arrivals (narrow dependency, nanosleep
// backoff), then hierarchical sparse softmax. No global barrier anywhere.
__global__ void __launch_bounds__(256) kall(
        float* __restrict__ out, const float* __restrict__ data,
        const float* __restrict__ ix, const float* __restrict__ iy,
        const float* __restrict__ ox, const float* __restrict__ oy,
        const float* __restrict__ la, const float* __restrict__ lm) {
    __shared__ float smin[8][32];
    __shared__ int   s_o[8][CAP];
    __shared__ float s_c2[8][CAP];

    int t = threadIdx.x, lane = t & 31, w = t >> 5;

    if (blockIdx.x < NPROD) {
        // ======================= PRODUCER =======================
        int p = blockIdx.x;
        int otile = p & 31, ib = p >> 5, ibt = ib * 32;

        // zero this block's out slice (32 float4), then signal g_zc
        if (w == 0) {
            ((float4*)out)[p * 32 + lane] = make_float4(0.f, 0.f, 0.f, 0.f);
            __threadfence();
            __syncwarp();
            if (lane == 0) atomicAdd(&g_zc, 1);
        }

        // tile: warp w covers o rows {w, w+8, w+16, w+24}; lane = i (coalesced).
        // IEEE div.rn kept — C is cancellation-amplified.
        float m = FLT_MAX;
#pragma unroll
        for (int k = 0; k < 4; k++) {
            int o = otile * 32 + w + 8 * k;
            int idx = o * In + ibt + lane;
            float c = (ix[idx] / iy[idx] + la[idx]) * (1.0f + lm[idx]) - ox[idx] / oy[idx];
            float c2 = c * c;
            g_c2[idx] = c2;                  // coalesced, same layout as inputs
            m = fminf(m, c2);
        }
        smin[w][lane] = m;                   // per-lane (=per-i) min over 4 o-rows
        __syncthreads();
        if (w == 0) {
            float mm = smin[0][lane];
#pragma unroll
            for (int ww = 1; ww < 8; ww++) mm = fminf(mm, smin[ww][lane]);
            g_tmin[(ibt + lane) * 32 + otile] = mm;
        }
        __threadfence();                     // make c2 + tmin visible device-wide
        __syncthreads();
        if (t == 0) atomicAdd(&g_cnt[ib], 1);
    } else {
        // ======================= CONSUMER =======================
        int cidx = blockIdx.x - NPROD;       // 0..127
        int ib = cidx >> 2, q = cidx & 3;    // 4 consumer blocks per i-block

        if (t == 0) {
            while (*(volatile unsigned*)&g_cnt[ib] < 32u) __nanosleep(128);
            while (*(volatile unsigned*)&g_zc < (unsigned)NPROD) __nanosleep(128);
        }
        __syncthreads();
        __threadfence();                     // acquire producers' writes

        unsigned lmask = (1u << lane) - 1u;

#pragma unroll 1
        for (int rr = 0; rr < 2; rr++) {
            int tid  = q * 16 + w * 2 + rr;  // 0..63 tasks per i-block
            int i    = ib * 32 + (tid >> 1);
            int half = tid & 1;

            // tile mins: one coalesced 128B load -> c2min
            float tv = g_tmin[i * 32 + lane];
            float mn = tv;
#pragma unroll
            for (int s = 16; s; s >>= 1) mn = fminf(mn, __shfl_xor_sync(0xffffffffu, mn, s));
            float c2min = mn;

            // per-b scalars (b = 64*half + lane + 32r) + keep threshold
            float dd[2], g2[2], Bm[2];
            float kmax = 0.f;
#pragma unroll
            for (int r = 0; r < 2; r++) {
                dd[r] = data[(size_t)(64 * half + lane + 32 * r) * In + i];
                float g = 1.0f / (1.0f + __expf(-dd[r]));
                g2[r] = g * g;
                float smax = rsq(fmaf(c2min, g2[r], EPSc));
                Bm[r] = -smax * L2E;
                float qq = smax - CUT_NATS;
                float keep = (qq > 0.f) ? (1.0f / (qq * qq) - EPSc) / g2[r] : FLT_MAX;
                kmax = fmaxf(kmax, keep);
            }
#pragma unroll
            for (int s = 16; s; s >>= 1) kmax = fmaxf(kmax, __shfl_xor_sync(0xffffffffu, kmax, s));
            float T = kmax;                  // conservative for this task's 64 b's

            // select tiles by tmin, exact-check only those (strided 32-sector loads)
            unsigned selmask = __ballot_sync(0xffffffffu, tv <= T);
            int base = 0;
            unsigned msk = selmask;
            while (msk) {
                int ot = __ffs(msk) - 1;     // warp-uniform
                msk &= msk - 1;
                float v = g_c2[(size_t)(ot * 32 + lane) * In + i];
                bool pred = (v <= T);
                unsigned bal = __ballot_sync(0xffffffffu, pred);
                if (pred) {
                    int pos = base + __popc(bal & lmask);
                    if (pos < CAP) {
                        s_o[w][pos]  = ot * 32 + lane;
                        s_c2[w][pos] = v;
                    }
                }
                base += __popc(bal);
            }
            int cnt = base;
            __syncwarp();

            if (cnt <= CAP) {
                // sparse path: lanes walk the shared tiny list (LDS broadcast)
                float S[2] = {0.f, 0.f};
                for (int k = 0; k < cnt; k++) {
                    float c2 = s_c2[w][k];
#pragma unroll
                    for (int r = 0; r < 2; r++)
                        S[r] += ex2(fmaf(rsq(fmaf(c2, g2[r], EPSc)), L2E, Bm[r]));
                }
                float coef[2];
#pragma unroll
                for (int r = 0; r < 2; r++) coef[r] = __fdividef(dd[r], S[r]);
                for (int k = 0; k < cnt; k++) {
                    int o = s_o[w][k];
                    float c2 = s_c2[w][k];
#pragma unroll
                    for (int r = 0; r < 2; r++) {
                        float e = ex2(fmaf(rsq(fmaf(c2, g2[r], EPSc)), L2E, Bm[r]));
                        atomicAdd(&out[(size_t)(64 * half + lane + 32 * r) * On + o],
                                  coef[r] * e);
                    }
                }
            } else {
                // dense fallback — correct for any data; statistically never taken
                float S[2] = {0.f, 0.f};
                for (int k = 0; k < In; k++) {
                    float c2 = g_c2[(size_t)k * In + i];   // broadcast per k
#pragma unroll
                    for (int r = 0; r < 2; r++)
                        S[r] += ex2(fmaf(rsq(fmaf(c2, g2[r], EPSc)), L2E, Bm[r]));
                }
                float coef[2];
#pragma unroll
                for (int r = 0; r < 2; r++) coef[r] = __fdividef(dd[r], S[r]);
                for (int k = 0; k < In; k++) {
                    float c2 = g_c2[(size_t)k * In + i];
#pragma unroll
                    for (int r = 0; r < 2; r++) {
                        float e = ex2(fmaf(rsq(fmaf(c2, g2[r], EPSc)), L2E, Bm[r]));
                        atomicAdd(&out[(size_t)(64 * half + lane + 32 * r) * On + k],
                                  coef[r] * e);
                    }
                }
            }
            __syncwarp();                    // s_o/s_c2 reuse across rr
        }

        // last consumer resets ALL counters (everyone has passed every gate)
        __syncthreads();
        if (t == 0) {
            unsigned r = atomicAdd(&g_ccnt, 1);
            if (r == NCONS - 1) {
#pragma unroll
                for (int j = 0; j < 32; j++) atomicExch(&g_cnt[j], 0u);
                atomicExch(&g_zc, 0u);
                atomicExch(&g_ccnt, 0u);
            }
        }
    }
}

extern "C" void kernel_launch(void* const* d_in, const int* in_sizes, int n_in,
                              void* d_out, int out_size) {
    const float* data = (const float*)d_in[0];
    const float* ix   = (const float*)d_in[1];
    const float* iy   = (const float*)d_in[2];
    const float* ox   = (const float*)d_in[3];
    const float* oy   = (const float*)d_in[4];
    const float* la   = (const float*)d_in[5];
    const float* lm   = (const float*)d_in[6];
    float* out = (float*)d_out;

    kall<<<NPROD + NCONS, 256>>>(out, data, ix, iy, ox, oy, la, lm);
}